// round 2
// baseline (speedup 1.0000x reference)
#include <cuda_runtime.h>
#include <cstdint>

// ---------------------------------------------------------------------------
// BiMambaLayer on GB300 — Round 1 baseline: full fp32, no tensor cores yet.
// Structure: run forward mamba block, backward mamba block (direction flag in
// conv+scan only; no flips materialized), combine with 2 layernorms, FFN, final LN.
// ---------------------------------------------------------------------------

namespace {
constexpr int kB   = 8;
constexpr int kL   = 4096;
constexpr int kDM  = 512;
constexpr int kDI  = 1024;
constexpr int kDXZ = 2048;
constexpr int kN   = 16;   // D_STATE
constexpr int kR   = 32;   // DT_RANK
constexpr int kDBC = 64;   // R + 2N
constexpr int kFF  = 2048;
constexpr int kT   = kB * kL;  // 32768 tokens
}

// Scratch (static device globals; allocation inside kernel_launch is forbidden)
__device__ float g_xz [(size_t)kT * kDXZ];  // 256 MB ; also reused as FFN hidden
__device__ float g_xc [(size_t)kT * kDI];   // 128 MB
__device__ float g_dbc[(size_t)kT * kDBC];  //   8 MB
__device__ float g_dt [(size_t)kT * kDI];   // 128 MB
__device__ float g_y  [(size_t)kT * kDI];   // 128 MB
__device__ float g_mf [(size_t)kT * kDM];   //  64 MB ; reused as ff output
__device__ float g_mb [(size_t)kT * kDM];   //  64 MB
__device__ float g_h  [(size_t)kT * kDM];   //  64 MB

// ---------------------------------------------------------------------------
// Generic GEMM: C[M,N] = A[M,K] (row stride lda) * W[N,K]^T  (+ epilogue)
// EPI: 0 = none, 1 = softplus(acc + bias), 2 = gelu_tanh(acc + bias), 3 = acc + bias
// BM=128 BN=64 BK=16, 256 threads, 8x4 per-thread microtile.
// Requires: M%128==0, N%64==0, K%16==0 (true for all call sites here).
// ---------------------------------------------------------------------------
template<int EPI>
__global__ void __launch_bounds__(256) gemm_k(
    const float* __restrict__ A, int lda,
    const float* __restrict__ W,
    const float* __restrict__ bias,
    float* __restrict__ C, int M, int N, int K)
{
  constexpr int BM = 128, BN = 64, BK = 16;
  __shared__ float As[BK][BM];
  __shared__ float Ws[BK][BN];

  const int tid = threadIdx.x;
  const int bm = blockIdx.y * BM;
  const int bn = blockIdx.x * BN;
  const int tx = tid & 15;   // N dim: 16 * 4 = 64
  const int ty = tid >> 4;   // M dim: 16 * 8 = 128

  float acc[8][4];
  #pragma unroll
  for (int i = 0; i < 8; i++)
    #pragma unroll
    for (int j = 0; j < 4; j++) acc[i][j] = 0.f;

  for (int k0 = 0; k0 < K; k0 += BK) {
    // Load A tile: 128 rows x 16 cols = 512 float4, 2 per thread.
    #pragma unroll
    for (int i = 0; i < 2; i++) {
      int idx = tid * 2 + i;          // 0..511
      int r = idx >> 2;               // row 0..127
      int c = (idx & 3) << 2;         // col 0,4,8,12
      float4 v = *reinterpret_cast<const float4*>(&A[(size_t)(bm + r) * lda + k0 + c]);
      As[c + 0][r] = v.x; As[c + 1][r] = v.y; As[c + 2][r] = v.z; As[c + 3][r] = v.w;
    }
    // Load W tile: 64 rows x 16 cols = 256 float4, 1 per thread.
    {
      int r = tid >> 2;               // row 0..63
      int c = (tid & 3) << 2;
      float4 v = *reinterpret_cast<const float4*>(&W[(size_t)(bn + r) * K + k0 + c]);
      Ws[c + 0][r] = v.x; Ws[c + 1][r] = v.y; Ws[c + 2][r] = v.z; Ws[c + 3][r] = v.w;
    }
    __syncthreads();

    #pragma unroll
    for (int k = 0; k < BK; k++) {
      float a[8], w[4];
      #pragma unroll
      for (int i = 0; i < 8; i++) a[i] = As[k][ty * 8 + i];
      #pragma unroll
      for (int j = 0; j < 4; j++) w[j] = Ws[k][tx * 4 + j];
      #pragma unroll
      for (int i = 0; i < 8; i++)
        #pragma unroll
        for (int j = 0; j < 4; j++)
          acc[i][j] = fmaf(a[i], w[j], acc[i][j]);
    }
    __syncthreads();
  }

  #pragma unroll
  for (int i = 0; i < 8; i++) {
    int row = bm + ty * 8 + i;
    #pragma unroll
    for (int j = 0; j < 4; j++) {
      int col = bn + tx * 4 + j;
      float v = acc[i][j];
      if (EPI == 1) {
        v += __ldg(&bias[col]);
        // softplus, numerically stable: max(x,0) + log1p(exp(-|x|))
        v = fmaxf(v, 0.f) + log1pf(__expf(-fabsf(v)));
      } else if (EPI == 2) {
        v += __ldg(&bias[col]);
        float t = tanhf(0.7978845608028654f * (v + 0.044715f * v * v * v));
        v = 0.5f * v * (1.f + t);
      } else if (EPI == 3) {
        v += __ldg(&bias[col]);
      }
      C[(size_t)row * N + col] = v;
    }
  }
}

// ---------------------------------------------------------------------------
// Depthwise causal conv (k=4) + bias + silu. dir=+1 forward, dir=-1 backward
// (backward == conv on time-flipped sequence, written back at original
//  positions => mirrored stencil with zero padding on the far side).
// ---------------------------------------------------------------------------
__global__ void conv_silu_k(const float* __restrict__ cw,
                            const float* __restrict__ cb, int dir)
{
  int i = blockIdx.x * blockDim.x + threadIdx.x;   // token*1024 + d
  int d = i & (kDI - 1);
  int tok = i >> 10;
  int pos = tok & (kL - 1);
  float acc = __ldg(&cb[d]);
  #pragma unroll
  for (int j = 0; j < 4; j++) {
    int o = (dir > 0) ? (j - 3) : (3 - j);
    int p = pos + o;
    if (p >= 0 && p < kL)
      acc = fmaf(__ldg(&cw[d * 4 + j]), g_xz[(size_t)(tok + o) * kDXZ + d], acc);
  }
  g_xc[i] = acc / (1.f + __expf(-acc));   // silu
}

// ---------------------------------------------------------------------------
// Selective scan. Warp = 2 channels (16 lanes each, lane%16 = state index n).
// Fused epilogue: y = (scan + xc*D) * silu(z).
// ---------------------------------------------------------------------------
__global__ void scan_k(const float* __restrict__ A_log,
                       const float* __restrict__ Dp, int dir)
{
  int gw   = (blockIdx.x * blockDim.x + threadIdx.x) >> 5;
  int lane = threadIdx.x & 31;
  int half = lane >> 4;
  int n    = lane & 15;
  int ch   = gw * 2 + half;          // 0..8191
  int b    = ch >> 10;
  int d    = ch & (kDI - 1);

  float A  = -__expf(__ldg(&A_log[d * kN + n]));
  float Dv = __ldg(&Dp[d]);
  float h  = 0.f;
  const size_t tokbase = (size_t)b * kL;

  for (int u = 0; u < kL; ++u) {
    int pos = (dir > 0) ? u : (kL - 1 - u);
    size_t tok = tokbase + pos;
    float dtv = g_dt [tok * kDI  + d];
    float xv  = g_xc [tok * kDI  + d];
    float Bv  = g_dbc[tok * kDBC + kR + n];
    float Cv  = g_dbc[tok * kDBC + kR + kN + n];
    float a   = __expf(dtv * A);
    h = fmaf(a, h, dtv * xv * Bv);
    float p = h * Cv;
    p += __shfl_xor_sync(0xffffffffu, p, 1);
    p += __shfl_xor_sync(0xffffffffu, p, 2);
    p += __shfl_xor_sync(0xffffffffu, p, 4);
    p += __shfl_xor_sync(0xffffffffu, p, 8);
    if (n == 0) {
      float zv = g_xz[tok * kDXZ + kDI + d];
      float sz = zv / (1.f + __expf(-zv));
      g_y[tok * kDI + d] = (p + xv * Dv) * sz;
    }
  }
}

// ---------------------------------------------------------------------------
// LayerNorm helpers (warp per row, 512 features = 16 floats/lane as 4 float4)
// ---------------------------------------------------------------------------
__device__ __forceinline__ float warp_sum(float v) {
  v += __shfl_xor_sync(0xffffffffu, v, 16);
  v += __shfl_xor_sync(0xffffffffu, v, 8);
  v += __shfl_xor_sync(0xffffffffu, v, 4);
  v += __shfl_xor_sync(0xffffffffu, v, 2);
  v += __shfl_xor_sync(0xffffffffu, v, 1);
  return v;
}

// h = 0.5 * ( LN(x+mf; gf,bf) + LN(x+mb; gb,bb) )
__global__ void ln_combine_k(const float* __restrict__ x,
    const float* __restrict__ gf, const float* __restrict__ bf,
    const float* __restrict__ gb, const float* __restrict__ bb)
{
  int row  = blockIdx.x * (blockDim.x >> 5) + (threadIdx.x >> 5);
  int lane = threadIdx.x & 31;
  const float* xr = x    + (size_t)row * kDM;
  const float* fr = g_mf + (size_t)row * kDM;
  const float* br = g_mb + (size_t)row * kDM;

  float u[16], v[16];
  float su = 0.f, sv = 0.f;
  #pragma unroll
  for (int k = 0; k < 4; k++) {
    int idx = (k * 32 + lane) * 4;
    float4 a  = *reinterpret_cast<const float4*>(xr + idx);
    float4 m1 = *reinterpret_cast<const float4*>(fr + idx);
    float4 m2 = *reinterpret_cast<const float4*>(br + idx);
    u[k*4+0]=a.x+m1.x; u[k*4+1]=a.y+m1.y; u[k*4+2]=a.z+m1.z; u[k*4+3]=a.w+m1.w;
    v[k*4+0]=a.x+m2.x; v[k*4+1]=a.y+m2.y; v[k*4+2]=a.z+m2.z; v[k*4+3]=a.w+m2.w;
    #pragma unroll
    for (int c = 0; c < 4; c++) { su += u[k*4+c]; sv += v[k*4+c]; }
  }
  float muU = warp_sum(su) * (1.f / kDM);
  float muV = warp_sum(sv) * (1.f / kDM);
  float qu = 0.f, qv = 0.f;
  #pragma unroll
  for (int c = 0; c < 16; c++) {
    float du = u[c] - muU, dv = v[c] - muV;
    qu += du * du; qv += dv * dv;
  }
  float rsU = rsqrtf(warp_sum(qu) * (1.f / kDM) + 1e-5f);
  float rsV = rsqrtf(warp_sum(qv) * (1.f / kDM) + 1e-5f);

  float* hr = g_h + (size_t)row * kDM;
  #pragma unroll
  for (int k = 0; k < 4; k++) {
    int idx = (k * 32 + lane) * 4;
    float4 o;
    #pragma unroll
    for (int c = 0; c < 4; c++) {
      int f = idx + c;
      float a = (u[k*4+c] - muU) * rsU * __ldg(&gf[f]) + __ldg(&bf[f]);
      float bvv = (v[k*4+c] - muV) * rsV * __ldg(&gb[f]) + __ldg(&bb[f]);
      ((float*)&o)[c] = 0.5f * (a + bvv);
    }
    *reinterpret_cast<float4*>(hr + idx) = o;
  }
}

// out = LN(h + ff; g,b)
__global__ void ln_final_k(const float* __restrict__ ff,
    const float* __restrict__ g, const float* __restrict__ bia,
    float* __restrict__ out)
{
  int row  = blockIdx.x * (blockDim.x >> 5) + (threadIdx.x >> 5);
  int lane = threadIdx.x & 31;
  const float* hr = g_h + (size_t)row * kDM;
  const float* fr = ff  + (size_t)row * kDM;

  float u[16];
  float su = 0.f;
  #pragma unroll
  for (int k = 0; k < 4; k++) {
    int idx = (k * 32 + lane) * 4;
    float4 a  = *reinterpret_cast<const float4*>(hr + idx);
    float4 m1 = *reinterpret_cast<const float4*>(fr + idx);
    u[k*4+0]=a.x+m1.x; u[k*4+1]=a.y+m1.y; u[k*4+2]=a.z+m1.z; u[k*4+3]=a.w+m1.w;
    #pragma unroll
    for (int c = 0; c < 4; c++) su += u[k*4+c];
  }
  float mu = warp_sum(su) * (1.f / kDM);
  float q = 0.f;
  #pragma unroll
  for (int c = 0; c < 16; c++) { float d = u[c] - mu; q += d * d; }
  float rs = rsqrtf(warp_sum(q) * (1.f / kDM) + 1e-5f);

  float* orow = out + (size_t)row * kDM;
  #pragma unroll
  for (int k = 0; k < 4; k++) {
    int idx = (k * 32 + lane) * 4;
    float4 o;
    #pragma unroll
    for (int c = 0; c < 4; c++) {
      int f = idx + c;
      ((float*)&o)[c] = (u[k*4+c] - mu) * rs * __ldg(&g[f]) + __ldg(&bia[f]);
    }
    *reinterpret_cast<float4*>(orow + idx) = o;
  }
}

// ---------------------------------------------------------------------------
// Launch
// ---------------------------------------------------------------------------
extern "C" void kernel_launch(void* const* d_in, const int* in_sizes, int n_in,
                              void* d_out, int out_size)
{
  const float* x = (const float*)d_in[0];
  // per-block params: in_w, conv_w, conv_b, xproj_w, dt_w, dt_b, A_log, D, out_w
  const float* const* Pf = (const float* const*)&d_in[1];   // indices 1..9
  const float* const* Pb = (const float* const*)&d_in[10];  // indices 10..18
  const float* ln_f_g  = (const float*)d_in[19];
  const float* ln_f_b  = (const float*)d_in[20];
  const float* ln_b_g  = (const float*)d_in[21];
  const float* ln_b_b  = (const float*)d_in[22];
  const float* ln_ff_g = (const float*)d_in[23];
  const float* ln_ff_b = (const float*)d_in[24];
  const float* ffn_w1  = (const float*)d_in[25];
  const float* ffn_b1  = (const float*)d_in[26];
  const float* ffn_w2  = (const float*)d_in[27];
  const float* ffn_b2  = (const float*)d_in[28];
  float* out = (float*)d_out;

  void *p_xz, *p_xc, *p_dbc, *p_dt, *p_y, *p_mf, *p_mb, *p_h;
  cudaGetSymbolAddress(&p_xz,  g_xz);
  cudaGetSymbolAddress(&p_xc,  g_xc);
  cudaGetSymbolAddress(&p_dbc, g_dbc);
  cudaGetSymbolAddress(&p_dt,  g_dt);
  cudaGetSymbolAddress(&p_y,   g_y);
  cudaGetSymbolAddress(&p_mf,  g_mf);
  cudaGetSymbolAddress(&p_mb,  g_mb);
  cudaGetSymbolAddress(&p_h,   g_h);

  const dim3 blk(256);
  const int rowsY = kT / 128;

  auto run_block = [&](const float* const* P, float* mout, int dir) {
    // 1) xz = x @ in_w^T            [T,2048]
    gemm_k<0><<<dim3(kDXZ / 64, rowsY), blk>>>(x, kDM, P[0], nullptr,
                                               (float*)p_xz, kT, kDXZ, kDM);
    // 2) depthwise conv + silu -> xc [T,1024]
    conv_silu_k<<<(kT * kDI) / 256, blk>>>(P[1], P[2], dir);
    // 3) dbc = xc @ xproj_w^T       [T,64]
    gemm_k<0><<<dim3(kDBC / 64, rowsY), blk>>>((const float*)p_xc, kDI, P[3],
                                               nullptr, (float*)p_dbc, kT, kDBC, kDI);
    // 4) dt = softplus(dbc[:,:32] @ dt_w^T + dt_b)  [T,1024]
    gemm_k<1><<<dim3(kDI / 64, rowsY), blk>>>((const float*)p_dbc, kDBC, P[4],
                                              P[5], (float*)p_dt, kT, kDI, kR);
    // 5) scan (fused +xc*D, *silu(z)) -> y [T,1024]
    scan_k<<<512, blk>>>(P[6], P[7], dir);
    // 6) m = y @ out_w^T            [T,512]
    gemm_k<0><<<dim3(kDM / 64, rowsY), blk>>>((const float*)p_y, kDI, P[8],
                                              nullptr, mout, kT, kDM, kDI);
  };

  run_block(Pf, (float*)p_mf, +1);
  run_block(Pb, (float*)p_mb, -1);

  // h = 0.5*(LN(x+mf) + LN(x+mb))
  ln_combine_k<<<kT / 8, blk>>>(x, ln_f_g, ln_f_b, ln_b_g, ln_b_b);

  // FFN: hidden = gelu(h @ w1^T + b1) -> reuse g_xz; ff = hidden @ w2^T + b2 -> reuse g_mf
  gemm_k<2><<<dim3(kFF / 64, rowsY), blk>>>((const float*)p_h, kDM, ffn_w1,
                                            ffn_b1, (float*)p_xz, kT, kFF, kDM);
  gemm_k<3><<<dim3(kDM / 64, rowsY), blk>>>((const float*)p_xz, kFF, ffn_w2,
                                            ffn_b2, (float*)p_mf, kT, kDM, kFF);

  // out = LN(h + ff)
  ln_final_k<<<kT / 8, blk>>>((const float*)p_mf, ln_ff_g, ln_ff_b, out);
}

// round 4
// speedup vs baseline: 1.3965x; 1.3965x over previous
#include <cuda_runtime.h>
#include <cstdint>

// ---------------------------------------------------------------------------
// BiMambaLayer on GB300 — Round 2: GEMMs on tensor cores via mma.sync TF32.
// ---------------------------------------------------------------------------

namespace {
constexpr int kB   = 8;
constexpr int kL   = 4096;
constexpr int kDM  = 512;
constexpr int kDI  = 1024;
constexpr int kDXZ = 2048;
constexpr int kN   = 16;   // D_STATE
constexpr int kR   = 32;   // DT_RANK
constexpr int kDBC = 64;   // R + 2N
constexpr int kFF  = 2048;
constexpr int kT   = kB * kL;  // 32768 tokens
}

// Scratch
__device__ float g_xz [(size_t)kT * kDXZ];
__device__ float g_xc [(size_t)kT * kDI];
__device__ float g_dbc[(size_t)kT * kDBC];
__device__ float g_dt [(size_t)kT * kDI];
__device__ float g_y  [(size_t)kT * kDI];
__device__ float g_mf [(size_t)kT * kDM];
__device__ float g_mb [(size_t)kT * kDM];
__device__ float g_h  [(size_t)kT * kDM];

__device__ __forceinline__ uint32_t f2tf32(float x) {
  uint32_t r;
  asm("cvt.rna.tf32.f32 %0, %1;" : "=r"(r) : "f"(x));
  return r;
}

__device__ __forceinline__ void mma_tf32(float* d,
    uint32_t a0, uint32_t a1, uint32_t a2, uint32_t a3,
    uint32_t b0, uint32_t b1)
{
  asm volatile(
    "mma.sync.aligned.m16n8k8.row.col.f32.tf32.tf32.f32 "
    "{%0,%1,%2,%3}, {%4,%5,%6,%7}, {%8,%9}, {%0,%1,%2,%3};\n"
    : "+f"(d[0]), "+f"(d[1]), "+f"(d[2]), "+f"(d[3])
    : "r"(a0), "r"(a1), "r"(a2), "r"(a3), "r"(b0), "r"(b1));
}

// ---------------------------------------------------------------------------
// Tensor-core GEMM: C[M,N] = A[M,K](row stride lda) * W[N,K]^T (+ epilogue)
// EPI: 0 none, 1 softplus(+bias), 2 gelu(+bias), 3 +bias
// BM=128 BN=64 BK=32, 128 threads (4 warps, 2x2), warp tile 64x32.
// smem holds TF32 values, k-permuted within each k8 group so fragment loads
// are vector lds.64: slot = r*36 + (k>>3)*8 + 2*(k&3) + ((k>>2)&1).
// Requires M%128==0, N%64==0, K%32==0.
// ---------------------------------------------------------------------------
template<int EPI>
__global__ void __launch_bounds__(128) gemm_tc(
    const float* __restrict__ A, int lda,
    const float* __restrict__ W,
    const float* __restrict__ bias,
    float* __restrict__ C, int M, int N, int K)
{
  constexpr int BM = 128, BN = 64, BK = 32, ST = 36;
  __shared__ uint32_t As[BM * ST];
  __shared__ uint32_t Ws[BN * ST];

  const int tid  = threadIdx.x;
  const int lane = tid & 31;
  const int wid  = tid >> 5;
  const int wm   = (wid & 1) * 64;
  const int wn   = (wid >> 1) * 32;
  const size_t bm = (size_t)blockIdx.y * BM;
  const int bn   = blockIdx.x * BN;
  const int g4   = lane >> 2;       // groupID 0..7
  const int t4   = lane & 3;        // tid in group

  float acc[4][4][4];
  #pragma unroll
  for (int i = 0; i < 4; i++)
    #pragma unroll
    for (int j = 0; j < 4; j++)
      #pragma unroll
      for (int c = 0; c < 4; c++) acc[i][j][c] = 0.f;

  float4 aR[8];
  float4 wR[4];

  auto ldg_tiles = [&](int k0) {
    #pragma unroll
    for (int i = 0; i < 8; i++) {
      int idx = tid + 128 * i;
      int r = idx >> 3, c4 = (idx & 7) << 2;
      aR[i] = *reinterpret_cast<const float4*>(&A[(bm + r) * (size_t)lda + k0 + c4]);
    }
    #pragma unroll
    for (int i = 0; i < 4; i++) {
      int idx = tid + 128 * i;
      int r = idx >> 3, c4 = (idx & 7) << 2;
      wR[i] = *reinterpret_cast<const float4*>(&W[(size_t)(bn + r) * K + k0 + c4]);
    }
  };

  auto sts_tiles = [&]() {
    #pragma unroll
    for (int i = 0; i < 8; i++) {
      int idx = tid + 128 * i;
      int r = idx >> 3, c4 = (idx & 7) << 2;
      uint32_t* p = &As[r * ST + ((c4 >> 3) << 3) + ((c4 >> 2) & 1)];
      p[0] = f2tf32(aR[i].x); p[2] = f2tf32(aR[i].y);
      p[4] = f2tf32(aR[i].z); p[6] = f2tf32(aR[i].w);
    }
    #pragma unroll
    for (int i = 0; i < 4; i++) {
      int idx = tid + 128 * i;
      int r = idx >> 3, c4 = (idx & 7) << 2;
      uint32_t* p = &Ws[r * ST + ((c4 >> 3) << 3) + ((c4 >> 2) & 1)];
      p[0] = f2tf32(wR[i].x); p[2] = f2tf32(wR[i].y);
      p[4] = f2tf32(wR[i].z); p[6] = f2tf32(wR[i].w);
    }
  };

  ldg_tiles(0);
  sts_tiles();
  __syncthreads();

  for (int k0 = 0;;) {
    const int knext = k0 + BK;
    const bool more = knext < K;
    if (more) ldg_tiles(knext);

    #pragma unroll
    for (int kk = 0; kk < 4; kk++) {
      uint32_t af[4][4];
      #pragma unroll
      for (int mi = 0; mi < 4; mi++) {
        int r = wm + mi * 16 + g4;
        const uint32_t* p = &As[r * ST + kk * 8 + 2 * t4];
        uint2 lo = *reinterpret_cast<const uint2*>(p);
        uint2 hi = *reinterpret_cast<const uint2*>(p + 8 * ST);
        af[mi][0] = lo.x; af[mi][2] = lo.y;
        af[mi][1] = hi.x; af[mi][3] = hi.y;
      }
      #pragma unroll
      for (int nj = 0; nj < 4; nj++) {
        int n = wn + nj * 8 + g4;
        uint2 b = *reinterpret_cast<const uint2*>(&Ws[n * ST + kk * 8 + 2 * t4]);
        #pragma unroll
        for (int mi = 0; mi < 4; mi++)
          mma_tf32(acc[mi][nj], af[mi][0], af[mi][1], af[mi][2], af[mi][3], b.x, b.y);
      }
    }
    __syncthreads();
    if (!more) break;
    sts_tiles();
    __syncthreads();
    k0 = knext;
  }

  // Epilogue
  #pragma unroll
  for (int mi = 0; mi < 4; mi++) {
    #pragma unroll
    for (int nj = 0; nj < 4; nj++) {
      size_t r0 = bm + wm + mi * 16 + g4;
      int c0 = bn + wn + nj * 8 + 2 * t4;
      #pragma unroll
      for (int half = 0; half < 2; half++) {
        size_t row = r0 + half * 8;
        float2 v;
        v.x = acc[mi][nj][half * 2 + 0];
        v.y = acc[mi][nj][half * 2 + 1];
        if (EPI == 1) {
          v.x += __ldg(&bias[c0]);     v.y += __ldg(&bias[c0 + 1]);
          v.x = fmaxf(v.x, 0.f) + log1pf(__expf(-fabsf(v.x)));
          v.y = fmaxf(v.y, 0.f) + log1pf(__expf(-fabsf(v.y)));
        } else if (EPI == 2) {
          v.x += __ldg(&bias[c0]);     v.y += __ldg(&bias[c0 + 1]);
          float tx = tanhf(0.7978845608028654f * (v.x + 0.044715f * v.x * v.x * v.x));
          float ty = tanhf(0.7978845608028654f * (v.y + 0.044715f * v.y * v.y * v.y));
          v.x = 0.5f * v.x * (1.f + tx);
          v.y = 0.5f * v.y * (1.f + ty);
        } else if (EPI == 3) {
          v.x += __ldg(&bias[c0]);     v.y += __ldg(&bias[c0 + 1]);
        }
        *reinterpret_cast<float2*>(&C[row * N + c0]) = v;
      }
    }
  }
}

// ---------------------------------------------------------------------------
// Depthwise causal conv (k=4) + bias + silu; dir=+1 fwd, -1 bwd (mirrored).
// ---------------------------------------------------------------------------
__global__ void conv_silu_k(const float* __restrict__ cw,
                            const float* __restrict__ cb, int dir)
{
  int i = blockIdx.x * blockDim.x + threadIdx.x;
  int d = i & (kDI - 1);
  int tok = i >> 10;
  int pos = tok & (kL - 1);
  float acc = __ldg(&cb[d]);
  #pragma unroll
  for (int j = 0; j < 4; j++) {
    int o = (dir > 0) ? (j - 3) : (3 - j);
    int p = pos + o;
    if (p >= 0 && p < kL)
      acc = fmaf(__ldg(&cw[d * 4 + j]), g_xz[(size_t)(tok + o) * kDXZ + d], acc);
  }
  g_xc[i] = acc / (1.f + __expf(-acc));
}

// ---------------------------------------------------------------------------
// Selective scan, warp = 2 channels (16 state lanes each).
// ---------------------------------------------------------------------------
__global__ void scan_k(const float* __restrict__ A_log,
                       const float* __restrict__ Dp, int dir)
{
  int gw   = (blockIdx.x * blockDim.x + threadIdx.x) >> 5;
  int lane = threadIdx.x & 31;
  int half = lane >> 4;
  int n    = lane & 15;
  int ch   = gw * 2 + half;
  int b    = ch >> 10;
  int d    = ch & (kDI - 1);

  float A  = -__expf(__ldg(&A_log[d * kN + n]));
  float Dv = __ldg(&Dp[d]);
  float h  = 0.f;
  const size_t tokbase = (size_t)b * kL;

  for (int u = 0; u < kL; ++u) {
    int pos = (dir > 0) ? u : (kL - 1 - u);
    size_t tok = tokbase + pos;
    float dtv = g_dt [tok * kDI  + d];
    float xv  = g_xc [tok * kDI  + d];
    float Bv  = g_dbc[tok * kDBC + kR + n];
    float Cv  = g_dbc[tok * kDBC + kR + kN + n];
    float a   = __expf(dtv * A);
    h = fmaf(a, h, dtv * xv * Bv);
    float p = h * Cv;
    p += __shfl_xor_sync(0xffffffffu, p, 1);
    p += __shfl_xor_sync(0xffffffffu, p, 2);
    p += __shfl_xor_sync(0xffffffffu, p, 4);
    p += __shfl_xor_sync(0xffffffffu, p, 8);
    if (n == 0) {
      float zv = g_xz[tok * kDXZ + kDI + d];
      float sz = zv / (1.f + __expf(-zv));
      g_y[tok * kDI + d] = (p + xv * Dv) * sz;
    }
  }
}

// ---------------------------------------------------------------------------
// LayerNorms
// ---------------------------------------------------------------------------
__device__ __forceinline__ float warp_sum(float v) {
  v += __shfl_xor_sync(0xffffffffu, v, 16);
  v += __shfl_xor_sync(0xffffffffu, v, 8);
  v += __shfl_xor_sync(0xffffffffu, v, 4);
  v += __shfl_xor_sync(0xffffffffu, v, 2);
  v += __shfl_xor_sync(0xffffffffu, v, 1);
  return v;
}

__global__ void ln_combine_k(const float* __restrict__ x,
    const float* __restrict__ gf, const float* __restrict__ bf,
    const float* __restrict__ gb, const float* __restrict__ bb)
{
  int row  = blockIdx.x * (blockDim.x >> 5) + (threadIdx.x >> 5);
  int lane = threadIdx.x & 31;
  const float* xr = x    + (size_t)row * kDM;
  const float* fr = g_mf + (size_t)row * kDM;
  const float* br = g_mb + (size_t)row * kDM;

  float u[16], v[16];
  float su = 0.f, sv = 0.f;
  #pragma unroll
  for (int k = 0; k < 4; k++) {
    int idx = (k * 32 + lane) * 4;
    float4 a  = *reinterpret_cast<const float4*>(xr + idx);
    float4 m1 = *reinterpret_cast<const float4*>(fr + idx);
    float4 m2 = *reinterpret_cast<const float4*>(br + idx);
    u[k*4+0]=a.x+m1.x; u[k*4+1]=a.y+m1.y; u[k*4+2]=a.z+m1.z; u[k*4+3]=a.w+m1.w;
    v[k*4+0]=a.x+m2.x; v[k*4+1]=a.y+m2.y; v[k*4+2]=a.z+m2.z; v[k*4+3]=a.w+m2.w;
    #pragma unroll
    for (int c = 0; c < 4; c++) { su += u[k*4+c]; sv += v[k*4+c]; }
  }
  float muU = warp_sum(su) * (1.f / kDM);
  float muV = warp_sum(sv) * (1.f / kDM);
  float qu = 0.f, qv = 0.f;
  #pragma unroll
  for (int c = 0; c < 16; c++) {
    float du = u[c] - muU, dv = v[c] - muV;
    qu += du * du; qv += dv * dv;
  }
  float rsU = rsqrtf(warp_sum(qu) * (1.f / kDM) + 1e-5f);
  float rsV = rsqrtf(warp_sum(qv) * (1.f / kDM) + 1e-5f);

  float* hr = g_h + (size_t)row * kDM;
  #pragma unroll
  for (int k = 0; k < 4; k++) {
    int idx = (k * 32 + lane) * 4;
    float4 o;
    #pragma unroll
    for (int c = 0; c < 4; c++) {
      int f = idx + c;
      float a = (u[k*4+c] - muU) * rsU * __ldg(&gf[f]) + __ldg(&bf[f]);
      float bvv = (v[k*4+c] - muV) * rsV * __ldg(&gb[f]) + __ldg(&bb[f]);
      ((float*)&o)[c] = 0.5f * (a + bvv);
    }
    *reinterpret_cast<float4*>(hr + idx) = o;
  }
}

__global__ void ln_final_k(const float* __restrict__ ff,
    const float* __restrict__ g, const float* __restrict__ bia,
    float* __restrict__ out)
{
  int row  = blockIdx.x * (blockDim.x >> 5) + (threadIdx.x >> 5);
  int lane = threadIdx.x & 31;
  const float* hr = g_h + (size_t)row * kDM;
  const float* fr = ff  + (size_t)row * kDM;

  float u[16];
  float su = 0.f;
  #pragma unroll
  for (int k = 0; k < 4; k++) {
    int idx = (k * 32 + lane) * 4;
    float4 a  = *reinterpret_cast<const float4*>(hr + idx);
    float4 m1 = *reinterpret_cast<const float4*>(fr + idx);
    u[k*4+0]=a.x+m1.x; u[k*4+1]=a.y+m1.y; u[k*4+2]=a.z+m1.z; u[k*4+3]=a.w+m1.w;
    #pragma unroll
    for (int c = 0; c < 4; c++) su += u[k*4+c];
  }
  float mu = warp_sum(su) * (1.f / kDM);
  float q = 0.f;
  #pragma unroll
  for (int c = 0; c < 16; c++) { float d = u[c] - mu; q += d * d; }
  float rs = rsqrtf(warp_sum(q) * (1.f / kDM) + 1e-5f);

  float* orow = out + (size_t)row * kDM;
  #pragma unroll
  for (int k = 0; k < 4; k++) {
    int idx = (k * 32 + lane) * 4;
    float4 o;
    #pragma unroll
    for (int c = 0; c < 4; c++) {
      int f = idx + c;
      ((float*)&o)[c] = (u[k*4+c] - mu) * rs * __ldg(&g[f]) + __ldg(&bia[f]);
    }
    *reinterpret_cast<float4*>(orow + idx) = o;
  }
}

// ---------------------------------------------------------------------------
// Launch
// ---------------------------------------------------------------------------
extern "C" void kernel_launch(void* const* d_in, const int* in_sizes, int n_in,
                              void* d_out, int out_size)
{
  const float* x = (const float*)d_in[0];
  const float* const* Pf = (const float* const*)&d_in[1];
  const float* const* Pb = (const float* const*)&d_in[10];
  const float* ln_f_g  = (const float*)d_in[19];
  const float* ln_f_b  = (const float*)d_in[20];
  const float* ln_b_g  = (const float*)d_in[21];
  const float* ln_b_b  = (const float*)d_in[22];
  const float* ln_ff_g = (const float*)d_in[23];
  const float* ln_ff_b = (const float*)d_in[24];
  const float* ffn_w1  = (const float*)d_in[25];
  const float* ffn_b1  = (const float*)d_in[26];
  const float* ffn_w2  = (const float*)d_in[27];
  const float* ffn_b2  = (const float*)d_in[28];
  float* out = (float*)d_out;

  void *p_xz, *p_xc, *p_dbc, *p_dt, *p_y, *p_mf, *p_mb, *p_h;
  cudaGetSymbolAddress(&p_xz,  g_xz);
  cudaGetSymbolAddress(&p_xc,  g_xc);
  cudaGetSymbolAddress(&p_dbc, g_dbc);
  cudaGetSymbolAddress(&p_dt,  g_dt);
  cudaGetSymbolAddress(&p_y,   g_y);
  cudaGetSymbolAddress(&p_mf,  g_mf);
  cudaGetSymbolAddress(&p_mb,  g_mb);
  cudaGetSymbolAddress(&p_h,   g_h);

  const dim3 blk(128);
  const int rowsY = kT / 128;   // 256

  auto run_block = [&](const float* const* P, float* mout, int dir) {
    gemm_tc<0><<<dim3(kDXZ / 64, rowsY), blk>>>(x, kDM, P[0], nullptr,
                                                (float*)p_xz, kT, kDXZ, kDM);
    conv_silu_k<<<(kT * kDI) / 256, dim3(256)>>>(P[1], P[2], dir);
    gemm_tc<0><<<dim3(kDBC / 64, rowsY), blk>>>((const float*)p_xc, kDI, P[3],
                                                nullptr, (float*)p_dbc, kT, kDBC, kDI);
    gemm_tc<1><<<dim3(kDI / 64, rowsY), blk>>>((const float*)p_dbc, kDBC, P[4],
                                               P[5], (float*)p_dt, kT, kDI, kR);
    scan_k<<<512, dim3(256)>>>(P[6], P[7], dir);
    gemm_tc<0><<<dim3(kDM / 64, rowsY), blk>>>((const float*)p_y, kDI, P[8],
                                               nullptr, mout, kT, kDM, kDI);
  };

  run_block(Pf, (float*)p_mf, +1);
  run_block(Pb, (float*)p_mb, -1);

  ln_combine_k<<<kT / 8, dim3(256)>>>(x, ln_f_g, ln_f_b, ln_b_g, ln_b_b);

  gemm_tc<2><<<dim3(kFF / 64, rowsY), blk>>>((const float*)p_h, kDM, ffn_w1,
                                             ffn_b1, (float*)p_xz, kT, kFF, kDM);
  gemm_tc<3><<<dim3(kDM / 64, rowsY), blk>>>((const float*)p_xz, kFF, ffn_w2,
                                             ffn_b2, (float*)p_mf, kT, kDM, kFF);

  ln_final_k<<<kT / 8, dim3(256)>>>((const float*)p_mf, ln_ff_g, ln_ff_b, out);
}

// round 6
// speedup vs baseline: 1.5400x; 1.1027x over previous
#include <cuda_runtime.h>
#include <cstdint>

// ---------------------------------------------------------------------------
// BiMambaLayer on GB300 — Round 4: R2 base (known pass) + plain smem layout,
// scalar LDS.32 fragment loads with immediate offsets, STS.128 tile stores.
// 128 threads, BM=128 BN=64 BK=32, warp tile 64x32, reg prefetch.
// ---------------------------------------------------------------------------

namespace {
constexpr int kB   = 8;
constexpr int kL   = 4096;
constexpr int kDM  = 512;
constexpr int kDI  = 1024;
constexpr int kDXZ = 2048;
constexpr int kN   = 16;
constexpr int kR   = 32;
constexpr int kDBC = 64;
constexpr int kFF  = 2048;
constexpr int kT   = kB * kL;
}

__device__ float g_xz [(size_t)kT * kDXZ];
__device__ float g_xc [(size_t)kT * kDI];
__device__ float g_dbc[(size_t)kT * kDBC];
__device__ float g_dt [(size_t)kT * kDI];
__device__ float g_y  [(size_t)kT * kDI];
__device__ float g_mf [(size_t)kT * kDM];
__device__ float g_mb [(size_t)kT * kDM];
__device__ float g_h  [(size_t)kT * kDM];

__device__ __forceinline__ uint32_t f2tf32(float x) {
  uint32_t r;
  asm("cvt.rna.tf32.f32 %0, %1;" : "=r"(r) : "f"(x));
  return r;
}

__device__ __forceinline__ void mma_tf32(float* d,
    uint32_t a0, uint32_t a1, uint32_t a2, uint32_t a3,
    uint32_t b0, uint32_t b1)
{
  asm volatile(
    "mma.sync.aligned.m16n8k8.row.col.f32.tf32.tf32.f32 "
    "{%0,%1,%2,%3}, {%4,%5,%6,%7}, {%8,%9}, {%0,%1,%2,%3};\n"
    : "+f"(d[0]), "+f"(d[1]), "+f"(d[2]), "+f"(d[3])
    : "r"(a0), "r"(a1), "r"(a2), "r"(a3), "r"(b0), "r"(b1));
}

// ---------------------------------------------------------------------------
// C[M,N] = A[M,K](row stride lda) * W[N,K]^T (+ epilogue)
// EPI: 0 none, 1 softplus(+bias), 2 gelu(+bias), 3 +bias
// 128 threads = 4 warps (2x2), warp tile 64x32.
// smem: plain [row][k] layout, row stride ST=36 words.
// Requires M%128==0, N%64==0, K%32==0.
// ---------------------------------------------------------------------------
template<int EPI>
__global__ void __launch_bounds__(128, 3) gemm_tc(
    const float* __restrict__ A, int lda,
    const float* __restrict__ W,
    const float* __restrict__ bias,
    float* __restrict__ C, int M, int N, int K)
{
  constexpr int BM = 128, BN = 64, BK = 32, ST = 36;
  __shared__ uint32_t As[BM * ST];
  __shared__ uint32_t Ws[BN * ST];

  const int tid  = threadIdx.x;
  const int lane = tid & 31;
  const int wid  = tid >> 5;
  const int wm   = (wid & 1) * 64;
  const int wn   = (wid >> 1) * 32;
  const size_t bm = (size_t)blockIdx.y * BM;
  const int bn   = blockIdx.x * BN;
  const int g4   = lane >> 2;
  const int t4   = lane & 3;

  float acc[4][4][4];
  #pragma unroll
  for (int i = 0; i < 4; i++)
    #pragma unroll
    for (int j = 0; j < 4; j++)
      #pragma unroll
      for (int c = 0; c < 4; c++) acc[i][j][c] = 0.f;

  // Loader geometry (same indexing as R2): 8 A-float4 + 4 W-float4 per thread.
  const int ldR = tid >> 3;            // 0..15 (A) / used with +128*i
  const int ldC = (tid & 7) << 2;      // k-col 0,4,..,28

  float4 aR[8];
  float4 wR[4];

  auto ldg_tiles = [&](int k0) {
    #pragma unroll
    for (int i = 0; i < 8; i++) {
      int r = ldR + 16 * i;
      aR[i] = *reinterpret_cast<const float4*>(&A[(bm + r) * (size_t)lda + k0 + ldC]);
    }
    #pragma unroll
    for (int i = 0; i < 4; i++) {
      int r = ldR + 16 * i;
      wR[i] = *reinterpret_cast<const float4*>(&W[(size_t)(bn + r) * K + k0 + ldC]);
    }
  };

  auto sts_tiles = [&]() {
    #pragma unroll
    for (int i = 0; i < 8; i++) {
      int r = ldR + 16 * i;
      uint4 v = { f2tf32(aR[i].x), f2tf32(aR[i].y), f2tf32(aR[i].z), f2tf32(aR[i].w) };
      *reinterpret_cast<uint4*>(&As[r * ST + ldC]) = v;
    }
    #pragma unroll
    for (int i = 0; i < 4; i++) {
      int r = ldR + 16 * i;
      uint4 v = { f2tf32(wR[i].x), f2tf32(wR[i].y), f2tf32(wR[i].z), f2tf32(wR[i].w) };
      *reinterpret_cast<uint4*>(&Ws[r * ST + ldC]) = v;
    }
  };

  // Hoisted fragment base pointers (immediate offsets off these below).
  const uint32_t* aF = &As[(wm + g4) * ST + t4];
  const uint32_t* bF = &Ws[(wn + g4) * ST + t4];

  ldg_tiles(0);
  sts_tiles();
  __syncthreads();

  for (int k0 = 0; k0 < K; k0 += BK) {
    const bool more = (k0 + BK) < K;
    if (more) ldg_tiles(k0 + BK);

    #pragma unroll
    for (int kk = 0; kk < 4; kk++) {
      uint32_t a[4][4];
      uint32_t b[4][2];
      #pragma unroll
      for (int mi = 0; mi < 4; mi++) {
        const uint32_t* p = aF + mi * (16 * ST) + kk * 8;
        a[mi][0] = p[0];
        a[mi][1] = p[8 * ST];
        a[mi][2] = p[4];
        a[mi][3] = p[8 * ST + 4];
      }
      #pragma unroll
      for (int nj = 0; nj < 4; nj++) {
        const uint32_t* p = bF + nj * (8 * ST) + kk * 8;
        b[nj][0] = p[0];
        b[nj][1] = p[4];
      }
      #pragma unroll
      for (int mi = 0; mi < 4; mi++)
        #pragma unroll
        for (int nj = 0; nj < 4; nj++)
          mma_tf32(acc[mi][nj], a[mi][0], a[mi][1], a[mi][2], a[mi][3],
                   b[nj][0], b[nj][1]);
    }
    __syncthreads();
    if (more) {
      sts_tiles();
      __syncthreads();
    }
  }

  // Epilogue (identical to R2)
  #pragma unroll
  for (int mi = 0; mi < 4; mi++) {
    #pragma unroll
    for (int nj = 0; nj < 4; nj++) {
      size_t r0 = bm + wm + mi * 16 + g4;
      int c0 = bn + wn + nj * 8 + 2 * t4;
      #pragma unroll
      for (int half = 0; half < 2; half++) {
        size_t row = r0 + half * 8;
        float2 v;
        v.x = acc[mi][nj][half * 2 + 0];
        v.y = acc[mi][nj][half * 2 + 1];
        if (EPI == 1) {
          v.x += __ldg(&bias[c0]);     v.y += __ldg(&bias[c0 + 1]);
          v.x = fmaxf(v.x, 0.f) + log1pf(__expf(-fabsf(v.x)));
          v.y = fmaxf(v.y, 0.f) + log1pf(__expf(-fabsf(v.y)));
        } else if (EPI == 2) {
          v.x += __ldg(&bias[c0]);     v.y += __ldg(&bias[c0 + 1]);
          float tx = tanhf(0.7978845608028654f * (v.x + 0.044715f * v.x * v.x * v.x));
          float ty = tanhf(0.7978845608028654f * (v.y + 0.044715f * v.y * v.y * v.y));
          v.x = 0.5f * v.x * (1.f + tx);
          v.y = 0.5f * v.y * (1.f + ty);
        } else if (EPI == 3) {
          v.x += __ldg(&bias[c0]);     v.y += __ldg(&bias[c0 + 1]);
        }
        *reinterpret_cast<float2*>(&C[row * N + c0]) = v;
      }
    }
  }
}

// ---------------------------------------------------------------------------
// Depthwise causal conv (k=4) + bias + silu; dir=+1 fwd, -1 bwd (mirrored).
// ---------------------------------------------------------------------------
__global__ void conv_silu_k(const float* __restrict__ cw,
                            const float* __restrict__ cb, int dir)
{
  int i = blockIdx.x * blockDim.x + threadIdx.x;
  int d = i & (kDI - 1);
  int tok = i >> 10;
  int pos = tok & (kL - 1);
  float acc = __ldg(&cb[d]);
  #pragma unroll
  for (int j = 0; j < 4; j++) {
    int o = (dir > 0) ? (j - 3) : (3 - j);
    int p = pos + o;
    if (p >= 0 && p < kL)
      acc = fmaf(__ldg(&cw[d * 4 + j]), g_xz[(size_t)(tok + o) * kDXZ + d], acc);
  }
  g_xc[i] = acc / (1.f + __expf(-acc));
}

// ---------------------------------------------------------------------------
// Selective scan, warp = 2 channels (16 state lanes each).
// ---------------------------------------------------------------------------
__global__ void scan_k(const float* __restrict__ A_log,
                       const float* __restrict__ Dp, int dir)
{
  int gw   = (blockIdx.x * blockDim.x + threadIdx.x) >> 5;
  int lane = threadIdx.x & 31;
  int half = lane >> 4;
  int n    = lane & 15;
  int ch   = gw * 2 + half;
  int b    = ch >> 10;
  int d    = ch & (kDI - 1);

  float A  = -__expf(__ldg(&A_log[d * kN + n]));
  float Dv = __ldg(&Dp[d]);
  float h  = 0.f;
  const size_t tokbase = (size_t)b * kL;

  for (int u = 0; u < kL; ++u) {
    int pos = (dir > 0) ? u : (kL - 1 - u);
    size_t tok = tokbase + pos;
    float dtv = g_dt [tok * kDI  + d];
    float xv  = g_xc [tok * kDI  + d];
    float Bv  = g_dbc[tok * kDBC + kR + n];
    float Cv  = g_dbc[tok * kDBC + kR + kN + n];
    float a   = __expf(dtv * A);
    h = fmaf(a, h, dtv * xv * Bv);
    float p = h * Cv;
    p += __shfl_xor_sync(0xffffffffu, p, 1);
    p += __shfl_xor_sync(0xffffffffu, p, 2);
    p += __shfl_xor_sync(0xffffffffu, p, 4);
    p += __shfl_xor_sync(0xffffffffu, p, 8);
    if (n == 0) {
      float zv = g_xz[tok * kDXZ + kDI + d];
      float sz = zv / (1.f + __expf(-zv));
      g_y[tok * kDI + d] = (p + xv * Dv) * sz;
    }
  }
}

// ---------------------------------------------------------------------------
// LayerNorms
// ---------------------------------------------------------------------------
__device__ __forceinline__ float warp_sum(float v) {
  v += __shfl_xor_sync(0xffffffffu, v, 16);
  v += __shfl_xor_sync(0xffffffffu, v, 8);
  v += __shfl_xor_sync(0xffffffffu, v, 4);
  v += __shfl_xor_sync(0xffffffffu, v, 2);
  v += __shfl_xor_sync(0xffffffffu, v, 1);
  return v;
}

__global__ void ln_combine_k(const float* __restrict__ x,
    const float* __restrict__ gf, const float* __restrict__ bf,
    const float* __restrict__ gb, const float* __restrict__ bb)
{
  int row  = blockIdx.x * (blockDim.x >> 5) + (threadIdx.x >> 5);
  int lane = threadIdx.x & 31;
  const float* xr = x    + (size_t)row * kDM;
  const float* fr = g_mf + (size_t)row * kDM;
  const float* br = g_mb + (size_t)row * kDM;

  float u[16], v[16];
  float su = 0.f, sv = 0.f;
  #pragma unroll
  for (int k = 0; k < 4; k++) {
    int idx = (k * 32 + lane) * 4;
    float4 a  = *reinterpret_cast<const float4*>(xr + idx);
    float4 m1 = *reinterpret_cast<const float4*>(fr + idx);
    float4 m2 = *reinterpret_cast<const float4*>(br + idx);
    u[k*4+0]=a.x+m1.x; u[k*4+1]=a.y+m1.y; u[k*4+2]=a.z+m1.z; u[k*4+3]=a.w+m1.w;
    v[k*4+0]=a.x+m2.x; v[k*4+1]=a.y+m2.y; v[k*4+2]=a.z+m2.z; v[k*4+3]=a.w+m2.w;
    #pragma unroll
    for (int c = 0; c < 4; c++) { su += u[k*4+c]; sv += v[k*4+c]; }
  }
  float muU = warp_sum(su) * (1.f / kDM);
  float muV = warp_sum(sv) * (1.f / kDM);
  float qu = 0.f, qv = 0.f;
  #pragma unroll
  for (int c = 0; c < 16; c++) {
    float du = u[c] - muU, dv = v[c] - muV;
    qu += du * du; qv += dv * dv;
  }
  float rsU = rsqrtf(warp_sum(qu) * (1.f / kDM) + 1e-5f);
  float rsV = rsqrtf(warp_sum(qv) * (1.f / kDM) + 1e-5f);

  float* hr = g_h + (size_t)row * kDM;
  #pragma unroll
  for (int k = 0; k < 4; k++) {
    int idx = (k * 32 + lane) * 4;
    float4 o;
    #pragma unroll
    for (int c = 0; c < 4; c++) {
      int f = idx + c;
      float a = (u[k*4+c] - muU) * rsU * __ldg(&gf[f]) + __ldg(&bf[f]);
      float bvv = (v[k*4+c] - muV) * rsV * __ldg(&gb[f]) + __ldg(&bb[f]);
      ((float*)&o)[c] = 0.5f * (a + bvv);
    }
    *reinterpret_cast<float4*>(hr + idx) = o;
  }
}

__global__ void ln_final_k(const float* __restrict__ ff,
    const float* __restrict__ g, const float* __restrict__ bia,
    float* __restrict__ out)
{
  int row  = blockIdx.x * (blockDim.x >> 5) + (threadIdx.x >> 5);
  int lane = threadIdx.x & 31;
  const float* hr = g_h + (size_t)row * kDM;
  const float* fr = ff  + (size_t)row * kDM;

  float u[16];
  float su = 0.f;
  #pragma unroll
  for (int k = 0; k < 4; k++) {
    int idx = (k * 32 + lane) * 4;
    float4 a  = *reinterpret_cast<const float4*>(hr + idx);
    float4 m1 = *reinterpret_cast<const float4*>(fr + idx);
    u[k*4+0]=a.x+m1.x; u[k*4+1]=a.y+m1.y; u[k*4+2]=a.z+m1.z; u[k*4+3]=a.w+m1.w;
    #pragma unroll
    for (int c = 0; c < 4; c++) su += u[k*4+c];
  }
  float mu = warp_sum(su) * (1.f / kDM);
  float q = 0.f;
  #pragma unroll
  for (int c = 0; c < 16; c++) { float d = u[c] - mu; q += d * d; }
  float rs = rsqrtf(warp_sum(q) * (1.f / kDM) + 1e-5f);

  float* orow = out + (size_t)row * kDM;
  #pragma unroll
  for (int k = 0; k < 4; k++) {
    int idx = (k * 32 + lane) * 4;
    float4 o;
    #pragma unroll
    for (int c = 0; c < 4; c++) {
      int f = idx + c;
      ((float*)&o)[c] = (u[k*4+c] - mu) * rs * __ldg(&g[f]) + __ldg(&bia[f]);
    }
    *reinterpret_cast<float4*>(orow + idx) = o;
  }
}

// ---------------------------------------------------------------------------
// Launch
// ---------------------------------------------------------------------------
extern "C" void kernel_launch(void* const* d_in, const int* in_sizes, int n_in,
                              void* d_out, int out_size)
{
  const float* x = (const float*)d_in[0];
  const float* const* Pf = (const float* const*)&d_in[1];
  const float* const* Pb = (const float* const*)&d_in[10];
  const float* ln_f_g  = (const float*)d_in[19];
  const float* ln_f_b  = (const float*)d_in[20];
  const float* ln_b_g  = (const float*)d_in[21];
  const float* ln_b_b  = (const float*)d_in[22];
  const float* ln_ff_g = (const float*)d_in[23];
  const float* ln_ff_b = (const float*)d_in[24];
  const float* ffn_w1  = (const float*)d_in[25];
  const float* ffn_b1  = (const float*)d_in[26];
  const float* ffn_w2  = (const float*)d_in[27];
  const float* ffn_b2  = (const float*)d_in[28];
  float* out = (float*)d_out;

  void *p_xz, *p_xc, *p_dbc, *p_dt, *p_y, *p_mf, *p_mb, *p_h;
  cudaGetSymbolAddress(&p_xz,  g_xz);
  cudaGetSymbolAddress(&p_xc,  g_xc);
  cudaGetSymbolAddress(&p_dbc, g_dbc);
  cudaGetSymbolAddress(&p_dt,  g_dt);
  cudaGetSymbolAddress(&p_y,   g_y);
  cudaGetSymbolAddress(&p_mf,  g_mf);
  cudaGetSymbolAddress(&p_mb,  g_mb);
  cudaGetSymbolAddress(&p_h,   g_h);

  const dim3 blk(128);
  const int rowsY = kT / 128;   // 256

  auto run_block = [&](const float* const* P, float* mout, int dir) {
    gemm_tc<0><<<dim3(kDXZ / 64, rowsY), blk>>>(x, kDM, P[0], nullptr,
                                                (float*)p_xz, kT, kDXZ, kDM);
    conv_silu_k<<<(kT * kDI) / 256, dim3(256)>>>(P[1], P[2], dir);
    gemm_tc<0><<<dim3(kDBC / 64, rowsY), blk>>>((const float*)p_xc, kDI, P[3],
                                                nullptr, (float*)p_dbc, kT, kDBC, kDI);
    gemm_tc<1><<<dim3(kDI / 64, rowsY), blk>>>((const float*)p_dbc, kDBC, P[4],
                                               P[5], (float*)p_dt, kT, kDI, kR);
    scan_k<<<512, dim3(256)>>>(P[6], P[7], dir);
    gemm_tc<0><<<dim3(kDM / 64, rowsY), blk>>>((const float*)p_y, kDI, P[8],
                                               nullptr, mout, kT, kDM, kDI);
  };

  run_block(Pf, (float*)p_mf, +1);
  run_block(Pb, (float*)p_mb, -1);

  ln_combine_k<<<kT / 8, dim3(256)>>>(x, ln_f_g, ln_f_b, ln_b_g, ln_b_b);

  gemm_tc<2><<<dim3(kFF / 64, rowsY), blk>>>((const float*)p_h, kDM, ffn_w1,
                                             ffn_b1, (float*)p_xz, kT, kFF, kDM);
  gemm_tc<3><<<dim3(kDM / 64, rowsY), blk>>>((const float*)p_xz, kFF, ffn_w2,
                                             ffn_b2, (float*)p_mf, kT, kDM, kFF);

  ln_final_k<<<kT / 8, dim3(256)>>>((const float*)p_mf, ln_ff_g, ln_ff_b, out);
}